// round 2
// baseline (speedup 1.0000x reference)
#include <cuda_runtime.h>
#include <cuda_bf16.h>

#define NNODE 100000
#define EMAX  1600000
#define CDIM 64

__device__ float g_h[NNODE * CDIM];
__device__ float g_agg[NNODE * CDIM];
__device__ int   g_src[EMAX];
__device__ int   g_dst[EMAX];
__device__ float g_pd[EMAX * 4];   // pos_diff, padded float4
__device__ int   g_mode;           // 1 = int64 indices, 0 = int32

__device__ __forceinline__ float elu_f(float v) {
    return v > 0.f ? v : expm1f(v);
}

// ------------------------------------------------------------------ probe index dtype
__global__ void probe_kernel(const int* __restrict__ w) {
    if (threadIdx.x == 0 && blockIdx.x == 0) {
        bool all_odd_zero = true;
        for (int i = 1; i < 64; i += 2)
            if (w[i] != 0) { all_odd_zero = false; break; }
        g_mode = all_odd_zero ? 1 : 0;
    }
}

// ------------------------------------------------------------------ convert indices + pos_diff
__global__ void convert_kernel(const int* __restrict__ w, const float* __restrict__ pos, int Ecnt) {
    int mode = g_mode;
    for (int e = blockIdx.x * blockDim.x + threadIdx.x; e < Ecnt; e += gridDim.x * blockDim.x) {
        int s, d;
        if (mode) { s = w[2 * e]; d = w[2 * (Ecnt + e)]; }
        else      { s = w[e];     d = w[Ecnt + e]; }
        // defensive clamp (avoid wild pointers if detection were ever wrong)
        s = min(max(s, 0), NNODE - 1);
        d = min(max(d, 0), NNODE - 1);
        g_src[e] = s;
        g_dst[e] = d;
        float4 pd;
        pd.x = pos[s * 3 + 0] - pos[d * 3 + 0];
        pd.y = pos[s * 3 + 1] - pos[d * 3 + 1];
        pd.z = pos[s * 3 + 2] - pos[d * 3 + 2];
        pd.w = 0.f;
        reinterpret_cast<float4*>(g_pd)[e] = pd;
    }
}

// ------------------------------------------------------------------ zero agg
__global__ void zero_agg_kernel(int n4) {
    float4* p = reinterpret_cast<float4*>(g_agg);
    for (int i = blockIdx.x * blockDim.x + threadIdx.x; i < n4; i += gridDim.x * blockDim.x)
        p[i] = make_float4(0.f, 0.f, 0.f, 0.f);
}

// ------------------------------------------------------------------ encoder
__global__ void encoder_kernel(const float* __restrict__ x,
                               const float* __restrict__ W0, const float* __restrict__ b0,
                               const float* __restrict__ W1, const float* __restrict__ b1,
                               int Nn) {
    __shared__ float sW1[4096];   // packed float2: (col j, col j+32)
    __shared__ float sW0[192];
    __shared__ float sb0[64];
    __shared__ float sb1[64];
    for (int t = threadIdx.x; t < 4096; t += blockDim.x) {
        int k = t >> 6, idx = t & 63, j = idx >> 1, half = idx & 1;
        sW1[t] = W1[k * 64 + j + (half << 5)];
    }
    for (int t = threadIdx.x; t < 192; t += blockDim.x) sW0[t] = W0[t];
    if (threadIdx.x < 64) { sb0[threadIdx.x] = b0[threadIdx.x]; sb1[threadIdx.x] = b1[threadIdx.x]; }
    __syncthreads();

    const float2* W1p = reinterpret_cast<const float2*>(sW1);
    int lane = threadIdx.x & 31;
    int wid  = threadIdx.x >> 5;
    int wg = blockIdx.x * (blockDim.x >> 5) + wid;
    int ws = gridDim.x * (blockDim.x >> 5);
    for (int n = wg; n < Nn; n += ws) {
        float x0 = x[n * 3 + 0], x1 = x[n * 3 + 1], x2 = x[n * 3 + 2];
        float hid0 = elu_f(x0 * sW0[lane]      + x1 * sW0[64 + lane]      + x2 * sW0[128 + lane]      + sb0[lane]);
        float hid1 = elu_f(x0 * sW0[lane + 32] + x1 * sW0[64 + lane + 32] + x2 * sW0[128 + lane + 32] + sb0[lane + 32]);
        float acc0 = sb1[lane], acc1 = sb1[lane + 32];
#pragma unroll
        for (int k = 0; k < 32; k++) {
            float v = __shfl_sync(0xffffffffu, hid0, k);
            float2 w = W1p[k * 32 + lane];
            acc0 += v * w.x; acc1 += v * w.y;
        }
#pragma unroll
        for (int k = 0; k < 32; k++) {
            float v = __shfl_sync(0xffffffffu, hid1, k);
            float2 w = W1p[(32 + k) * 32 + lane];
            acc0 += v * w.x; acc1 += v * w.y;
        }
        g_h[n * 64 + lane] = acc0;
        g_h[n * 64 + 32 + lane] = acc1;
    }
}

// ------------------------------------------------------------------ edge MLP + scatter-add
// Folded first GEMM: x_nei·(W0a+W0c) + x_own·(W0b−W0c) + pos_diff·W0d
// Warp processes 4 edges; activations staged in per-warp SMEM as [64][4] (float4 reads).
__global__ void edge_kernel(const float* __restrict__ E0, const float* __restrict__ eb0,
                            const float* __restrict__ E1, const float* __restrict__ eb1,
                            int Ecnt) {
    extern __shared__ float sm[];
    float* sWA = sm;             // 4096  (W0a + W0c, packed float2)
    float* sWB = sWA + 4096;     // 4096  (W0b - W0c)
    float* sW1 = sWB + 4096;     // 4096  (eW1)
    float* sWp = sW1 + 4096;     // 192   (W0d)
    float* sb0 = sWp + 192;      // 64
    float* sb1 = sb0 + 64;       // 64
    float* stage = sb1 + 64;     // 8 warps * 528 floats

    for (int t = threadIdx.x; t < 4096; t += blockDim.x) {
        int k = t >> 6, idx = t & 63, j = idx >> 1, half = idx & 1, col = j + (half << 5);
        float wC = E0[(128 + k) * 64 + col];
        sWA[t] = E0[k * 64 + col] + wC;
        sWB[t] = E0[(64 + k) * 64 + col] - wC;
        sW1[t] = E1[k * 64 + col];
    }
    for (int t = threadIdx.x; t < 192; t += blockDim.x) {
        int k = t >> 6, idx = t & 63, j = idx >> 1, half = idx & 1, col = j + (half << 5);
        sWp[t] = E0[(192 + k) * 64 + col];
    }
    if (threadIdx.x < 64) { sb0[threadIdx.x] = eb0[threadIdx.x]; sb1[threadIdx.x] = eb1[threadIdx.x]; }
    __syncthreads();

    int lane = threadIdx.x & 31;
    int wid  = threadIdx.x >> 5;
    float* aS  = stage + wid * 528;   // [64][4] gathered x_nei (reused for hidden)
    float* oS  = aS + 256;            // [64][4] gathered x_own
    float* pdS = oS + 256;            // [3][4] pos_diff (+pad to 16)

    const float2* WAp = reinterpret_cast<const float2*>(sWA);
    const float2* WBp = reinterpret_cast<const float2*>(sWB);
    const float2* W1p = reinterpret_cast<const float2*>(sW1);
    const float2* Wpp = reinterpret_cast<const float2*>(sWp);
    const float4* aS4 = reinterpret_cast<const float4*>(aS);
    const float4* oS4 = reinterpret_cast<const float4*>(oS);
    const float4* pd4 = reinterpret_cast<const float4*>(pdS);

    int wg = blockIdx.x * (blockDim.x >> 5) + wid;
    int ws = gridDim.x * (blockDim.x >> 5);
    for (int base = wg * 4; base < Ecnt; base += ws * 4) {
        int dsts[4];
#pragma unroll
        for (int i = 0; i < 4; i++) {
            int e = base + i;
            if (e < Ecnt) {
                int s = g_src[e];
                int d = g_dst[e];
                dsts[i] = d;
                const float* hs = g_h + s * 64;
                const float* hd = g_h + d * 64;
                aS[lane * 4 + i]        = hs[lane];
                aS[(lane + 32) * 4 + i] = hs[lane + 32];
                oS[lane * 4 + i]        = hd[lane];
                oS[(lane + 32) * 4 + i] = hd[lane + 32];
                if (lane < 3) pdS[lane * 4 + i] = g_pd[e * 4 + lane];
            } else {
                dsts[i] = -1;
                aS[lane * 4 + i] = 0.f; aS[(lane + 32) * 4 + i] = 0.f;
                oS[lane * 4 + i] = 0.f; oS[(lane + 32) * 4 + i] = 0.f;
                if (lane < 3) pdS[lane * 4 + i] = 0.f;
            }
        }
        __syncwarp();

        float acc00 = sb0[lane],      acc10 = acc00, acc20 = acc00, acc30 = acc00;
        float acc01 = sb0[lane + 32], acc11 = acc01, acc21 = acc01, acc31 = acc01;
#pragma unroll 4
        for (int k = 0; k < 64; k++) {
            float2 wa = WAp[k * 32 + lane];
            float2 wb = WBp[k * 32 + lane];
            float4 av = aS4[k];
            float4 ov = oS4[k];
            acc00 += av.x * wa.x + ov.x * wb.x;  acc01 += av.x * wa.y + ov.x * wb.y;
            acc10 += av.y * wa.x + ov.y * wb.x;  acc11 += av.y * wa.y + ov.y * wb.y;
            acc20 += av.z * wa.x + ov.z * wb.x;  acc21 += av.z * wa.y + ov.z * wb.y;
            acc30 += av.w * wa.x + ov.w * wb.x;  acc31 += av.w * wa.y + ov.w * wb.y;
        }
#pragma unroll
        for (int k = 0; k < 3; k++) {
            float2 wp = Wpp[k * 32 + lane];
            float4 pv = pd4[k];
            acc00 += pv.x * wp.x; acc01 += pv.x * wp.y;
            acc10 += pv.y * wp.x; acc11 += pv.y * wp.y;
            acc20 += pv.z * wp.x; acc21 += pv.z * wp.y;
            acc30 += pv.w * wp.x; acc31 += pv.w * wp.y;
        }
        __syncwarp();
        aS[lane * 4 + 0] = elu_f(acc00); aS[(lane + 32) * 4 + 0] = elu_f(acc01);
        aS[lane * 4 + 1] = elu_f(acc10); aS[(lane + 32) * 4 + 1] = elu_f(acc11);
        aS[lane * 4 + 2] = elu_f(acc20); aS[(lane + 32) * 4 + 2] = elu_f(acc21);
        aS[lane * 4 + 3] = elu_f(acc30); aS[(lane + 32) * 4 + 3] = elu_f(acc31);
        __syncwarp();

        acc00 = sb1[lane];      acc10 = acc00; acc20 = acc00; acc30 = acc00;
        acc01 = sb1[lane + 32]; acc11 = acc01; acc21 = acc01; acc31 = acc01;
#pragma unroll 4
        for (int k = 0; k < 64; k++) {
            float2 w  = W1p[k * 32 + lane];
            float4 hv = aS4[k];
            acc00 += hv.x * w.x; acc01 += hv.x * w.y;
            acc10 += hv.y * w.x; acc11 += hv.y * w.y;
            acc20 += hv.z * w.x; acc21 += hv.z * w.y;
            acc30 += hv.w * w.x; acc31 += hv.w * w.y;
        }
        if (dsts[0] >= 0) { atomicAdd(&g_agg[dsts[0] * 64 + lane], acc00); atomicAdd(&g_agg[dsts[0] * 64 + 32 + lane], acc01); }
        if (dsts[1] >= 0) { atomicAdd(&g_agg[dsts[1] * 64 + lane], acc10); atomicAdd(&g_agg[dsts[1] * 64 + 32 + lane], acc11); }
        if (dsts[2] >= 0) { atomicAdd(&g_agg[dsts[2] * 64 + lane], acc20); atomicAdd(&g_agg[dsts[2] * 64 + 32 + lane], acc21); }
        if (dsts[3] >= 0) { atomicAdd(&g_agg[dsts[3] * 64 + lane], acc30); atomicAdd(&g_agg[dsts[3] * 64 + 32 + lane], acc31); }
        __syncwarp();
    }
}

// ------------------------------------------------------------------ node update
__global__ void node_kernel(const float* __restrict__ W0, const float* __restrict__ b0,
                            const float* __restrict__ W1, const float* __restrict__ b1,
                            int Nn) {
    extern __shared__ float sm[];
    float* sW0 = sm;           // 8192
    float* sW1 = sm + 8192;    // 4096
    float* sb0 = sm + 12288;   // 64
    float* sb1 = sm + 12352;   // 64
    for (int t = threadIdx.x; t < 8192; t += blockDim.x) {
        int k = t >> 6, idx = t & 63, j = idx >> 1, half = idx & 1;
        sW0[t] = W0[k * 64 + j + (half << 5)];
    }
    for (int t = threadIdx.x; t < 4096; t += blockDim.x) {
        int k = t >> 6, idx = t & 63, j = idx >> 1, half = idx & 1;
        sW1[t] = W1[k * 64 + j + (half << 5)];
    }
    if (threadIdx.x < 64) { sb0[threadIdx.x] = b0[threadIdx.x]; sb1[threadIdx.x] = b1[threadIdx.x]; }
    __syncthreads();

    const float2* W0p = reinterpret_cast<const float2*>(sW0);
    const float2* W1p = reinterpret_cast<const float2*>(sW1);
    int lane = threadIdx.x & 31, wid = threadIdx.x >> 5;
    int wg = blockIdx.x * (blockDim.x >> 5) + wid;
    int ws = gridDim.x * (blockDim.x >> 5);
    for (int n = wg; n < Nn; n += ws) {
        float h0 = g_h[n * 64 + lane],   h1 = g_h[n * 64 + 32 + lane];
        float a0 = g_agg[n * 64 + lane], a1 = g_agg[n * 64 + 32 + lane];
        float acc0 = sb0[lane], acc1 = sb0[lane + 32];
#pragma unroll
        for (int k = 0; k < 32; k++) { float v = __shfl_sync(~0u, h0, k); float2 w = W0p[k * 32 + lane];        acc0 += v * w.x; acc1 += v * w.y; }
#pragma unroll
        for (int k = 0; k < 32; k++) { float v = __shfl_sync(~0u, h1, k); float2 w = W0p[(32 + k) * 32 + lane]; acc0 += v * w.x; acc1 += v * w.y; }
#pragma unroll
        for (int k = 0; k < 32; k++) { float v = __shfl_sync(~0u, a0, k); float2 w = W0p[(64 + k) * 32 + lane]; acc0 += v * w.x; acc1 += v * w.y; }
#pragma unroll
        for (int k = 0; k < 32; k++) { float v = __shfl_sync(~0u, a1, k); float2 w = W0p[(96 + k) * 32 + lane]; acc0 += v * w.x; acc1 += v * w.y; }
        float hid0 = elu_f(acc0), hid1 = elu_f(acc1);
        acc0 = sb1[lane]; acc1 = sb1[lane + 32];
#pragma unroll
        for (int k = 0; k < 32; k++) { float v = __shfl_sync(~0u, hid0, k); float2 w = W1p[k * 32 + lane];        acc0 += v * w.x; acc1 += v * w.y; }
#pragma unroll
        for (int k = 0; k < 32; k++) { float v = __shfl_sync(~0u, hid1, k); float2 w = W1p[(32 + k) * 32 + lane]; acc0 += v * w.x; acc1 += v * w.y; }
        g_h[n * 64 + lane]      = h0 + acc0;
        g_h[n * 64 + 32 + lane] = h1 + acc1;
    }
}

// ------------------------------------------------------------------ decoder
__global__ void decoder_kernel(const float* __restrict__ W0, const float* __restrict__ b0,
                               const float* __restrict__ W1, const float* __restrict__ b1,
                               float* __restrict__ out, int Nn) {
    __shared__ float sW0[4096];
    __shared__ float sW1[192];
    __shared__ float sb0[64];
    __shared__ float sb1v[3];
    for (int t = threadIdx.x; t < 4096; t += blockDim.x) {
        int k = t >> 6, idx = t & 63, j = idx >> 1, half = idx & 1;
        sW0[t] = W0[k * 64 + j + (half << 5)];
    }
    for (int t = threadIdx.x; t < 192; t += blockDim.x) sW1[t] = W1[t];
    if (threadIdx.x < 64) sb0[threadIdx.x] = b0[threadIdx.x];
    if (threadIdx.x < 3)  sb1v[threadIdx.x] = b1[threadIdx.x];
    __syncthreads();

    const float2* W0p = reinterpret_cast<const float2*>(sW0);
    int lane = threadIdx.x & 31, wid = threadIdx.x >> 5;
    int wg = blockIdx.x * (blockDim.x >> 5) + wid;
    int ws = gridDim.x * (blockDim.x >> 5);
    for (int n = wg; n < Nn; n += ws) {
        float h0 = g_h[n * 64 + lane], h1 = g_h[n * 64 + 32 + lane];
        float acc0 = sb0[lane], acc1 = sb0[lane + 32];
#pragma unroll
        for (int k = 0; k < 32; k++) { float v = __shfl_sync(~0u, h0, k); float2 w = W0p[k * 32 + lane];        acc0 += v * w.x; acc1 += v * w.y; }
#pragma unroll
        for (int k = 0; k < 32; k++) { float v = __shfl_sync(~0u, h1, k); float2 w = W0p[(32 + k) * 32 + lane]; acc0 += v * w.x; acc1 += v * w.y; }
        float hid0 = elu_f(acc0), hid1 = elu_f(acc1);
        float p0 = hid0 * sW1[lane * 3 + 0] + hid1 * sW1[(lane + 32) * 3 + 0];
        float p1 = hid0 * sW1[lane * 3 + 1] + hid1 * sW1[(lane + 32) * 3 + 1];
        float p2 = hid0 * sW1[lane * 3 + 2] + hid1 * sW1[(lane + 32) * 3 + 2];
#pragma unroll
        for (int off = 16; off; off >>= 1) {
            p0 += __shfl_xor_sync(~0u, p0, off);
            p1 += __shfl_xor_sync(~0u, p1, off);
            p2 += __shfl_xor_sync(~0u, p2, off);
        }
        if (lane == 0) {
            out[n * 3 + 0] = p0 + sb1v[0];
            out[n * 3 + 1] = p1 + sb1v[1];
            out[n * 3 + 2] = p2 + sb1v[2];
        }
    }
}

// ------------------------------------------------------------------ launch
extern "C" void kernel_launch(void* const* d_in, const int* in_sizes, int n_in,
                              void* d_out, int out_size) {
    const float* x      = (const float*)d_in[0];
    const float* pos    = (const float*)d_in[1];
    const int*   ei     = (const int*)d_in[2];   // int32 OR int64; auto-detected on device
    const float* enc_W0 = (const float*)d_in[3];
    const float* enc_b0 = (const float*)d_in[4];
    const float* enc_W1 = (const float*)d_in[5];
    const float* enc_b1 = (const float*)d_in[6];
    const float* dec_W0 = (const float*)d_in[7];
    const float* dec_b0 = (const float*)d_in[8];
    const float* dec_W1 = (const float*)d_in[9];
    const float* dec_b1 = (const float*)d_in[10];
    const float* eW0    = (const float*)d_in[11];
    const float* eb0    = (const float*)d_in[12];
    const float* eW1    = (const float*)d_in[13];
    const float* eb1    = (const float*)d_in[14];
    const float* nW0    = (const float*)d_in[15];
    const float* nb0    = (const float*)d_in[16];
    const float* nW1    = (const float*)d_in[17];
    const float* nb1    = (const float*)d_in[18];

    int Nn   = in_sizes[0] / 3;
    int Ecnt = in_sizes[2] / 2;
    if (Ecnt > EMAX) Ecnt = EMAX;
    float* out = (float*)d_out;

    const int EDGE_SMEM = 16832 * 4;   // 67328 B
    const int NODE_SMEM = 12416 * 4;   // 49664 B
    cudaFuncSetAttribute(edge_kernel, cudaFuncAttributeMaxDynamicSharedMemorySize, EDGE_SMEM);
    cudaFuncSetAttribute(node_kernel, cudaFuncAttributeMaxDynamicSharedMemorySize, NODE_SMEM);

    const int NB = 444, TPB = 256;

    probe_kernel<<<1, 32>>>(ei);
    convert_kernel<<<NB, TPB>>>(ei, pos, Ecnt);
    encoder_kernel<<<NB, TPB>>>(x, enc_W0, enc_b0, enc_W1, enc_b1, Nn);
    for (int l = 0; l < 2; l++) {
        zero_agg_kernel<<<NB, TPB>>>(Nn * 64 / 4);
        edge_kernel<<<NB, TPB, EDGE_SMEM>>>(eW0 + (size_t)l * 195 * 64, eb0 + l * 64,
                                            eW1 + (size_t)l * 64 * 64,  eb1 + l * 64,
                                            Ecnt);
        node_kernel<<<NB, TPB, NODE_SMEM>>>(nW0 + (size_t)l * 128 * 64, nb0 + l * 64,
                                            nW1 + (size_t)l * 64 * 64,  nb1 + l * 64,
                                            Nn);
    }
    decoder_kernel<<<NB, TPB>>>(dec_W0, dec_b0, dec_W1, dec_b1, out, Nn);
}

// round 3
// speedup vs baseline: 1.0838x; 1.0838x over previous
#include <cuda_runtime.h>
#include <cuda_bf16.h>

#define NNODE 100000
#define EMAX  1600000
#define CDIM 64

__device__ float g_h[NNODE * CDIM];
__device__ float g_agg[NNODE * CDIM];
__device__ int   g_src[EMAX];
__device__ int   g_dst[EMAX];
__device__ float g_pd[EMAX * 4];   // pos_diff, padded float4
__device__ int   g_mode;           // 1 = int64 indices, 0 = int32

__device__ __forceinline__ float elu_f(float v) {
    return v > 0.f ? v : expm1f(v);
}

// packed fp32x2 helpers (sm_100+): d += a * b elementwise on two packed floats
__device__ __forceinline__ void ffma2(unsigned long long& d, unsigned long long a, unsigned long long b) {
    asm("fma.rn.f32x2 %0, %1, %2, %0;" : "+l"(d) : "l"(a), "l"(b));
}
__device__ __forceinline__ float usum(unsigned long long v) {
    float lo, hi;
    asm("mov.b64 {%0,%1}, %2;" : "=f"(lo), "=f"(hi) : "l"(v));
    return lo + hi;
}

// ------------------------------------------------------------------ probe index dtype
__global__ void probe_kernel(const int* __restrict__ w) {
    if (threadIdx.x == 0 && blockIdx.x == 0) {
        bool all_odd_zero = true;
        for (int i = 1; i < 64; i += 2)
            if (w[i] != 0) { all_odd_zero = false; break; }
        g_mode = all_odd_zero ? 1 : 0;
    }
}

// ------------------------------------------------------------------ convert indices + pos_diff
__global__ void convert_kernel(const int* __restrict__ w, const float* __restrict__ pos, int Ecnt) {
    int mode = g_mode;
    for (int e = blockIdx.x * blockDim.x + threadIdx.x; e < Ecnt; e += gridDim.x * blockDim.x) {
        int s, d;
        if (mode) { s = w[2 * e]; d = w[2 * (Ecnt + e)]; }
        else      { s = w[e];     d = w[Ecnt + e]; }
        s = min(max(s, 0), NNODE - 1);
        d = min(max(d, 0), NNODE - 1);
        g_src[e] = s;
        g_dst[e] = d;
        float4 pd;
        pd.x = pos[s * 3 + 0] - pos[d * 3 + 0];
        pd.y = pos[s * 3 + 1] - pos[d * 3 + 1];
        pd.z = pos[s * 3 + 2] - pos[d * 3 + 2];
        pd.w = 0.f;
        reinterpret_cast<float4*>(g_pd)[e] = pd;
    }
}

// ------------------------------------------------------------------ zero agg
__global__ void zero_agg_kernel(int n4) {
    float4* p = reinterpret_cast<float4*>(g_agg);
    for (int i = blockIdx.x * blockDim.x + threadIdx.x; i < n4; i += gridDim.x * blockDim.x)
        p[i] = make_float4(0.f, 0.f, 0.f, 0.f);
}

// ------------------------------------------------------------------ encoder
__global__ void encoder_kernel(const float* __restrict__ x,
                               const float* __restrict__ W0, const float* __restrict__ b0,
                               const float* __restrict__ W1, const float* __restrict__ b1,
                               int Nn) {
    __shared__ float sW1[4096];   // packed float2: (col j, col j+32)
    __shared__ float sW0[192];
    __shared__ float sb0[64];
    __shared__ float sb1[64];
    for (int t = threadIdx.x; t < 4096; t += blockDim.x) {
        int k = t >> 6, idx = t & 63, j = idx >> 1, half = idx & 1;
        sW1[t] = W1[k * 64 + j + (half << 5)];
    }
    for (int t = threadIdx.x; t < 192; t += blockDim.x) sW0[t] = W0[t];
    if (threadIdx.x < 64) { sb0[threadIdx.x] = b0[threadIdx.x]; sb1[threadIdx.x] = b1[threadIdx.x]; }
    __syncthreads();

    const float2* W1p = reinterpret_cast<const float2*>(sW1);
    int lane = threadIdx.x & 31;
    int wid  = threadIdx.x >> 5;
    int wg = blockIdx.x * (blockDim.x >> 5) + wid;
    int ws = gridDim.x * (blockDim.x >> 5);
    for (int n = wg; n < Nn; n += ws) {
        float x0 = x[n * 3 + 0], x1 = x[n * 3 + 1], x2 = x[n * 3 + 2];
        float hid0 = elu_f(x0 * sW0[lane]      + x1 * sW0[64 + lane]      + x2 * sW0[128 + lane]      + sb0[lane]);
        float hid1 = elu_f(x0 * sW0[lane + 32] + x1 * sW0[64 + lane + 32] + x2 * sW0[128 + lane + 32] + sb0[lane + 32]);
        float acc0 = sb1[lane], acc1 = sb1[lane + 32];
#pragma unroll
        for (int k = 0; k < 32; k++) {
            float v = __shfl_sync(0xffffffffu, hid0, k);
            float2 w = W1p[k * 32 + lane];
            acc0 += v * w.x; acc1 += v * w.y;
        }
#pragma unroll
        for (int k = 0; k < 32; k++) {
            float v = __shfl_sync(0xffffffffu, hid1, k);
            float2 w = W1p[(32 + k) * 32 + lane];
            acc0 += v * w.x; acc1 += v * w.y;
        }
        g_h[n * 64 + lane] = acc0;
        g_h[n * 64 + 32 + lane] = acc1;
    }
}

// ------------------------------------------------------------------ edge MLP + scatter-add (f32x2)
// Folded first GEMM: x_nei·(W0a+W0c) + x_own·(W0b−W0c) + pos_diff·W0d
// Packed along K: acc.lo accumulates even-k, acc.hi odd-k; halves summed at the end.
// SMEM weight layout: float4 per (kpair, lane) = (w[k0][j], w[k1][j], w[k0][j+32], w[k1][j+32]).
// Staging: float2 k-pairs per edge, row stride 5 (pad) to avoid bank conflicts.
__global__ void edge_kernel(const float* __restrict__ E0, const float* __restrict__ eb0,
                            const float* __restrict__ E1, const float* __restrict__ eb1,
                            int Ecnt) {
    extern __shared__ float sm[];
    float* sWA = sm;                 // 4096
    float* sWB = sm + 4096;          // 4096
    float* sW1 = sm + 8192;          // 4096
    float* sWp = sm + 12288;         // 256 (2 kpairs, k=3 padded with 0)
    float* sb0 = sm + 12544;         // 64
    float* sb1 = sm + 12608;         // 64
    float* stage = sm + 12672;       // 8 warps * 660 floats

    for (int t = threadIdx.x; t < 4096; t += blockDim.x) {
        int c = t & 3, lane_ = (t >> 2) & 31, kp = t >> 7;
        int k = 2 * kp + (c & 1);
        int col = lane_ + ((c & 2) ? 32 : 0);
        float wC = E0[(128 + k) * 64 + col];
        sWA[t] = E0[k * 64 + col] + wC;
        sWB[t] = E0[(64 + k) * 64 + col] - wC;
        sW1[t] = E1[k * 64 + col];
    }
    for (int t = threadIdx.x; t < 256; t += blockDim.x) {
        int c = t & 3, lane_ = (t >> 2) & 31, kp = t >> 7;
        int k = 2 * kp + (c & 1);
        int col = lane_ + ((c & 2) ? 32 : 0);
        sWp[t] = (k < 3) ? E0[(192 + k) * 64 + col] : 0.f;
    }
    if (threadIdx.x < 64) { sb0[threadIdx.x] = eb0[threadIdx.x]; sb1[threadIdx.x] = eb1[threadIdx.x]; }
    __syncthreads();

    int lane = threadIdx.x & 31;
    int wid  = threadIdx.x >> 5;
    float* wbase = stage + wid * 660;
    float2* aP  = reinterpret_cast<float2*>(wbase);        // 32 kpairs * 5, also hidden reuse
    float2* oP  = reinterpret_cast<float2*>(wbase + 320);  // 32 kpairs * 5
    float2* pdP = reinterpret_cast<float2*>(wbase + 640);  // 2 kpairs * 5

    const ulonglong2* WAv = reinterpret_cast<const ulonglong2*>(sWA);
    const ulonglong2* WBv = reinterpret_cast<const ulonglong2*>(sWB);
    const ulonglong2* W1v = reinterpret_cast<const ulonglong2*>(sW1);
    const ulonglong2* Wpv = reinterpret_cast<const ulonglong2*>(sWp);
    const unsigned long long* aU  = reinterpret_cast<const unsigned long long*>(aP);
    const unsigned long long* oU  = reinterpret_cast<const unsigned long long*>(oP);
    const unsigned long long* pdU = reinterpret_cast<const unsigned long long*>(pdP);
    float* hF = wbase;   // hidden staging (reuse aP region)

    int wg = blockIdx.x * (blockDim.x >> 5) + wid;
    int ws = gridDim.x * (blockDim.x >> 5);
    for (int base = wg * 4; base < Ecnt; base += ws * 4) {
        int dsts[4];
#pragma unroll
        for (int i = 0; i < 4; i++) {
            int e = base + i;
            if (e < Ecnt) {
                int s = g_src[e];
                int d = g_dst[e];
                dsts[i] = d;
                aP[lane * 5 + i] = reinterpret_cast<const float2*>(g_h + s * 64)[lane];
                oP[lane * 5 + i] = reinterpret_cast<const float2*>(g_h + d * 64)[lane];
                if (lane == 0) {
                    float4 pd = reinterpret_cast<const float4*>(g_pd)[e];
                    pdP[0 * 5 + i] = make_float2(pd.x, pd.y);
                    pdP[1 * 5 + i] = make_float2(pd.z, 0.f);
                }
            } else {
                dsts[i] = -1;
                aP[lane * 5 + i] = make_float2(0.f, 0.f);
                oP[lane * 5 + i] = make_float2(0.f, 0.f);
                if (lane == 0) {
                    pdP[0 * 5 + i] = make_float2(0.f, 0.f);
                    pdP[1 * 5 + i] = make_float2(0.f, 0.f);
                }
            }
        }
        __syncwarp();

        unsigned long long acc00 = 0ull, acc01 = 0ull, acc10 = 0ull, acc11 = 0ull;
        unsigned long long acc20 = 0ull, acc21 = 0ull, acc30 = 0ull, acc31 = 0ull;
#pragma unroll 4
        for (int kp = 0; kp < 32; kp++) {
            ulonglong2 wa = WAv[kp * 32 + lane];
            ulonglong2 wb = WBv[kp * 32 + lane];
            unsigned long long a0 = aU[kp * 5 + 0], a1 = aU[kp * 5 + 1];
            unsigned long long a2 = aU[kp * 5 + 2], a3 = aU[kp * 5 + 3];
            unsigned long long o0 = oU[kp * 5 + 0], o1 = oU[kp * 5 + 1];
            unsigned long long o2 = oU[kp * 5 + 2], o3 = oU[kp * 5 + 3];
            ffma2(acc00, a0, wa.x); ffma2(acc01, a0, wa.y);
            ffma2(acc10, a1, wa.x); ffma2(acc11, a1, wa.y);
            ffma2(acc20, a2, wa.x); ffma2(acc21, a2, wa.y);
            ffma2(acc30, a3, wa.x); ffma2(acc31, a3, wa.y);
            ffma2(acc00, o0, wb.x); ffma2(acc01, o0, wb.y);
            ffma2(acc10, o1, wb.x); ffma2(acc11, o1, wb.y);
            ffma2(acc20, o2, wb.x); ffma2(acc21, o2, wb.y);
            ffma2(acc30, o3, wb.x); ffma2(acc31, o3, wb.y);
        }
#pragma unroll
        for (int kp = 0; kp < 2; kp++) {
            ulonglong2 wp = Wpv[kp * 32 + lane];
            unsigned long long p0 = pdU[kp * 5 + 0], p1 = pdU[kp * 5 + 1];
            unsigned long long p2 = pdU[kp * 5 + 2], p3 = pdU[kp * 5 + 3];
            ffma2(acc00, p0, wp.x); ffma2(acc01, p0, wp.y);
            ffma2(acc10, p1, wp.x); ffma2(acc11, p1, wp.y);
            ffma2(acc20, p2, wp.x); ffma2(acc21, p2, wp.y);
            ffma2(acc30, p3, wp.x); ffma2(acc31, p3, wp.y);
        }

        float b0a = sb0[lane], b0b = sb0[lane + 32];
        float h00 = elu_f(usum(acc00) + b0a), h01 = elu_f(usum(acc01) + b0b);
        float h10 = elu_f(usum(acc10) + b0a), h11 = elu_f(usum(acc11) + b0b);
        float h20 = elu_f(usum(acc20) + b0a), h21 = elu_f(usum(acc21) + b0b);
        float h30 = elu_f(usum(acc30) + b0a), h31 = elu_f(usum(acc31) + b0b);
        __syncwarp();
        {
            int r0 = ((lane >> 1) * 5) * 2 + (lane & 1);          // k = lane
            int r1 = ((16 + (lane >> 1)) * 5) * 2 + (lane & 1);   // k = lane + 32
            hF[r0 + 0] = h00; hF[r1 + 0] = h01;
            hF[r0 + 2] = h10; hF[r1 + 2] = h11;
            hF[r0 + 4] = h20; hF[r1 + 4] = h21;
            hF[r0 + 6] = h30; hF[r1 + 6] = h31;
        }
        __syncwarp();

        acc00 = 0ull; acc01 = 0ull; acc10 = 0ull; acc11 = 0ull;
        acc20 = 0ull; acc21 = 0ull; acc30 = 0ull; acc31 = 0ull;
#pragma unroll 4
        for (int kp = 0; kp < 32; kp++) {
            ulonglong2 w1 = W1v[kp * 32 + lane];
            unsigned long long v0 = aU[kp * 5 + 0], v1 = aU[kp * 5 + 1];
            unsigned long long v2 = aU[kp * 5 + 2], v3 = aU[kp * 5 + 3];
            ffma2(acc00, v0, w1.x); ffma2(acc01, v0, w1.y);
            ffma2(acc10, v1, w1.x); ffma2(acc11, v1, w1.y);
            ffma2(acc20, v2, w1.x); ffma2(acc21, v2, w1.y);
            ffma2(acc30, v3, w1.x); ffma2(acc31, v3, w1.y);
        }
        float b1a = sb1[lane], b1b = sb1[lane + 32];
        if (dsts[0] >= 0) { atomicAdd(&g_agg[dsts[0] * 64 + lane], usum(acc00) + b1a); atomicAdd(&g_agg[dsts[0] * 64 + 32 + lane], usum(acc01) + b1b); }
        if (dsts[1] >= 0) { atomicAdd(&g_agg[dsts[1] * 64 + lane], usum(acc10) + b1a); atomicAdd(&g_agg[dsts[1] * 64 + 32 + lane], usum(acc11) + b1b); }
        if (dsts[2] >= 0) { atomicAdd(&g_agg[dsts[2] * 64 + lane], usum(acc20) + b1a); atomicAdd(&g_agg[dsts[2] * 64 + 32 + lane], usum(acc21) + b1b); }
        if (dsts[3] >= 0) { atomicAdd(&g_agg[dsts[3] * 64 + lane], usum(acc30) + b1a); atomicAdd(&g_agg[dsts[3] * 64 + 32 + lane], usum(acc31) + b1b); }
        __syncwarp();
    }
}

// ------------------------------------------------------------------ node update (f32x2)
// u = elu([h, agg] @ nW0 + nb0) @ nW1 + nb1 ; h = h + u
__global__ void node_kernel(const float* __restrict__ W0, const float* __restrict__ b0,
                            const float* __restrict__ W1, const float* __restrict__ b1,
                            int Nn) {
    extern __shared__ float sm[];
    float* sW0 = sm;                 // 8192 (64 kpairs)
    float* sW1 = sm + 8192;          // 4096 (32 kpairs)
    float* sb0 = sm + 12288;         // 64
    float* sb1 = sm + 12352;         // 64
    float* stage = sm + 12416;       // 8 warps * 640 floats

    for (int t = threadIdx.x; t < 8192; t += blockDim.x) {
        int c = t & 3, lane_ = (t >> 2) & 31, kp = t >> 7;
        int k = 2 * kp + (c & 1);
        int col = lane_ + ((c & 2) ? 32 : 0);
        sW0[t] = W0[k * 64 + col];
    }
    for (int t = threadIdx.x; t < 4096; t += blockDim.x) {
        int c = t & 3, lane_ = (t >> 2) & 31, kp = t >> 7;
        int k = 2 * kp + (c & 1);
        int col = lane_ + ((c & 2) ? 32 : 0);
        sW1[t] = W1[k * 64 + col];
    }
    if (threadIdx.x < 64) { sb0[threadIdx.x] = b0[threadIdx.x]; sb1[threadIdx.x] = b1[threadIdx.x]; }
    __syncthreads();

    int lane = threadIdx.x & 31;
    int wid  = threadIdx.x >> 5;
    float* wbase = stage + wid * 640;
    float2* nP = reinterpret_cast<float2*>(wbase);  // 64 kpairs * 5 (h then agg); hidden reuses first 32
    const ulonglong2* W0v = reinterpret_cast<const ulonglong2*>(sW0);
    const ulonglong2* W1v = reinterpret_cast<const ulonglong2*>(sW1);
    const unsigned long long* nU = reinterpret_cast<const unsigned long long*>(nP);
    float* hF = wbase;

    int wg = blockIdx.x * (blockDim.x >> 5) + wid;
    int ws = gridDim.x * (blockDim.x >> 5);
    for (int base = wg * 4; base < Nn; base += ws * 4) {
#pragma unroll
        for (int i = 0; i < 4; i++) {
            int n = base + i;
            if (n < Nn) {
                nP[lane * 5 + i]        = reinterpret_cast<const float2*>(g_h + n * 64)[lane];
                nP[(32 + lane) * 5 + i] = reinterpret_cast<const float2*>(g_agg + n * 64)[lane];
            } else {
                nP[lane * 5 + i]        = make_float2(0.f, 0.f);
                nP[(32 + lane) * 5 + i] = make_float2(0.f, 0.f);
            }
        }
        __syncwarp();

        unsigned long long acc00 = 0ull, acc01 = 0ull, acc10 = 0ull, acc11 = 0ull;
        unsigned long long acc20 = 0ull, acc21 = 0ull, acc30 = 0ull, acc31 = 0ull;
#pragma unroll 4
        for (int kp = 0; kp < 64; kp++) {
            ulonglong2 w = W0v[kp * 32 + lane];
            unsigned long long v0 = nU[kp * 5 + 0], v1 = nU[kp * 5 + 1];
            unsigned long long v2 = nU[kp * 5 + 2], v3 = nU[kp * 5 + 3];
            ffma2(acc00, v0, w.x); ffma2(acc01, v0, w.y);
            ffma2(acc10, v1, w.x); ffma2(acc11, v1, w.y);
            ffma2(acc20, v2, w.x); ffma2(acc21, v2, w.y);
            ffma2(acc30, v3, w.x); ffma2(acc31, v3, w.y);
        }
        float b0a = sb0[lane], b0b = sb0[lane + 32];
        float h00 = elu_f(usum(acc00) + b0a), h01 = elu_f(usum(acc01) + b0b);
        float h10 = elu_f(usum(acc10) + b0a), h11 = elu_f(usum(acc11) + b0b);
        float h20 = elu_f(usum(acc20) + b0a), h21 = elu_f(usum(acc21) + b0b);
        float h30 = elu_f(usum(acc30) + b0a), h31 = elu_f(usum(acc31) + b0b);
        __syncwarp();
        {
            int r0 = ((lane >> 1) * 5) * 2 + (lane & 1);
            int r1 = ((16 + (lane >> 1)) * 5) * 2 + (lane & 1);
            hF[r0 + 0] = h00; hF[r1 + 0] = h01;
            hF[r0 + 2] = h10; hF[r1 + 2] = h11;
            hF[r0 + 4] = h20; hF[r1 + 4] = h21;
            hF[r0 + 6] = h30; hF[r1 + 6] = h31;
        }
        __syncwarp();

        acc00 = 0ull; acc01 = 0ull; acc10 = 0ull; acc11 = 0ull;
        acc20 = 0ull; acc21 = 0ull; acc30 = 0ull; acc31 = 0ull;
#pragma unroll 4
        for (int kp = 0; kp < 32; kp++) {
            ulonglong2 w = W1v[kp * 32 + lane];
            unsigned long long v0 = nU[kp * 5 + 0], v1 = nU[kp * 5 + 1];
            unsigned long long v2 = nU[kp * 5 + 2], v3 = nU[kp * 5 + 3];
            ffma2(acc00, v0, w.x); ffma2(acc01, v0, w.y);
            ffma2(acc10, v1, w.x); ffma2(acc11, v1, w.y);
            ffma2(acc20, v2, w.x); ffma2(acc21, v2, w.y);
            ffma2(acc30, v3, w.x); ffma2(acc31, v3, w.y);
        }
        float b1a = sb1[lane], b1b = sb1[lane + 32];
#pragma unroll
        for (int i = 0; i < 4; i++) {
            int n = base + i;
            if (n < Nn) {
                float u0, u1;
                if (i == 0) { u0 = usum(acc00); u1 = usum(acc01); }
                else if (i == 1) { u0 = usum(acc10); u1 = usum(acc11); }
                else if (i == 2) { u0 = usum(acc20); u1 = usum(acc21); }
                else { u0 = usum(acc30); u1 = usum(acc31); }
                float old0 = g_h[n * 64 + lane];
                float old1 = g_h[n * 64 + 32 + lane];
                g_h[n * 64 + lane]      = old0 + u0 + b1a;
                g_h[n * 64 + 32 + lane] = old1 + u1 + b1b;
            }
        }
        __syncwarp();
    }
}

// ------------------------------------------------------------------ decoder
__global__ void decoder_kernel(const float* __restrict__ W0, const float* __restrict__ b0,
                               const float* __restrict__ W1, const float* __restrict__ b1,
                               float* __restrict__ out, int Nn) {
    __shared__ float sW0[4096];
    __shared__ float sW1[192];
    __shared__ float sb0[64];
    __shared__ float sb1v[3];
    for (int t = threadIdx.x; t < 4096; t += blockDim.x) {
        int k = t >> 6, idx = t & 63, j = idx >> 1, half = idx & 1;
        sW0[t] = W0[k * 64 + j + (half << 5)];
    }
    for (int t = threadIdx.x; t < 192; t += blockDim.x) sW1[t] = W1[t];
    if (threadIdx.x < 64) sb0[threadIdx.x] = b0[threadIdx.x];
    if (threadIdx.x < 3)  sb1v[threadIdx.x] = b1[threadIdx.x];
    __syncthreads();

    const float2* W0p = reinterpret_cast<const float2*>(sW0);
    int lane = threadIdx.x & 31, wid = threadIdx.x >> 5;
    int wg = blockIdx.x * (blockDim.x >> 5) + wid;
    int ws = gridDim.x * (blockDim.x >> 5);
    for (int n = wg; n < Nn; n += ws) {
        float h0 = g_h[n * 64 + lane], h1 = g_h[n * 64 + 32 + lane];
        float acc0 = sb0[lane], acc1 = sb0[lane + 32];
#pragma unroll
        for (int k = 0; k < 32; k++) { float v = __shfl_sync(~0u, h0, k); float2 w = W0p[k * 32 + lane];        acc0 += v * w.x; acc1 += v * w.y; }
#pragma unroll
        for (int k = 0; k < 32; k++) { float v = __shfl_sync(~0u, h1, k); float2 w = W0p[(32 + k) * 32 + lane]; acc0 += v * w.x; acc1 += v * w.y; }
        float hid0 = elu_f(acc0), hid1 = elu_f(acc1);
        float p0 = hid0 * sW1[lane * 3 + 0] + hid1 * sW1[(lane + 32) * 3 + 0];
        float p1 = hid0 * sW1[lane * 3 + 1] + hid1 * sW1[(lane + 32) * 3 + 1];
        float p2 = hid0 * sW1[lane * 3 + 2] + hid1 * sW1[(lane + 32) * 3 + 2];
#pragma unroll
        for (int off = 16; off; off >>= 1) {
            p0 += __shfl_xor_sync(~0u, p0, off);
            p1 += __shfl_xor_sync(~0u, p1, off);
            p2 += __shfl_xor_sync(~0u, p2, off);
        }
        if (lane == 0) {
            out[n * 3 + 0] = p0 + sb1v[0];
            out[n * 3 + 1] = p1 + sb1v[1];
            out[n * 3 + 2] = p2 + sb1v[2];
        }
    }
}

// ------------------------------------------------------------------ launch
extern "C" void kernel_launch(void* const* d_in, const int* in_sizes, int n_in,
                              void* d_out, int out_size) {
    const float* x      = (const float*)d_in[0];
    const float* pos    = (const float*)d_in[1];
    const int*   ei     = (const int*)d_in[2];   // int32 OR int64; auto-detected on device
    const float* enc_W0 = (const float*)d_in[3];
    const float* enc_b0 = (const float*)d_in[4];
    const float* enc_W1 = (const float*)d_in[5];
    const float* enc_b1 = (const float*)d_in[6];
    const float* dec_W0 = (const float*)d_in[7];
    const float* dec_b0 = (const float*)d_in[8];
    const float* dec_W1 = (const float*)d_in[9];
    const float* dec_b1 = (const float*)d_in[10];
    const float* eW0    = (const float*)d_in[11];
    const float* eb0    = (const float*)d_in[12];
    const float* eW1    = (const float*)d_in[13];
    const float* eb1    = (const float*)d_in[14];
    const float* nW0    = (const float*)d_in[15];
    const float* nb0    = (const float*)d_in[16];
    const float* nW1    = (const float*)d_in[17];
    const float* nb1    = (const float*)d_in[18];

    int Nn   = in_sizes[0] / 3;
    int Ecnt = in_sizes[2] / 2;
    if (Ecnt > EMAX) Ecnt = EMAX;
    float* out = (float*)d_out;

    const int EDGE_SMEM = (12672 + 8 * 660) * 4;   // 71808 B
    const int NODE_SMEM = (12416 + 8 * 640) * 4;   // 70144 B
    cudaFuncSetAttribute(edge_kernel, cudaFuncAttributeMaxDynamicSharedMemorySize, EDGE_SMEM);
    cudaFuncSetAttribute(node_kernel, cudaFuncAttributeMaxDynamicSharedMemorySize, NODE_SMEM);

    const int NB = 296, TPB = 256;

    probe_kernel<<<1, 32>>>(ei);
    convert_kernel<<<444, TPB>>>(ei, pos, Ecnt);
    encoder_kernel<<<444, TPB>>>(x, enc_W0, enc_b0, enc_W1, enc_b1, Nn);
    for (int l = 0; l < 2; l++) {
        zero_agg_kernel<<<444, TPB>>>(Nn * 64 / 4);
        edge_kernel<<<NB, TPB, EDGE_SMEM>>>(eW0 + (size_t)l * 195 * 64, eb0 + l * 64,
                                            eW1 + (size_t)l * 64 * 64,  eb1 + l * 64,
                                            Ecnt);
        node_kernel<<<NB, TPB, NODE_SMEM>>>(nW0 + (size_t)l * 128 * 64, nb0 + l * 64,
                                            nW1 + (size_t)l * 64 * 64,  nb1 + l * 64,
                                            Nn);
    }
    decoder_kernel<<<444, TPB>>>(dec_W0, dec_b0, dec_W1, dec_b1, out, Nn);
}

// round 4
// speedup vs baseline: 3.4771x; 3.2081x over previous
#include <cuda_runtime.h>
#include <cuda_bf16.h>

#define NNODE 100000
#define EMAX  1600000
#define CDIM 64

__device__ __align__(16) float g_h[NNODE * CDIM];
__device__ __align__(16) float g_agg[NNODE * CDIM];   // per-layer: segment_sum of hidden
__device__ __align__(16) float g_PA[NNODE * CDIM];
__device__ __align__(16) float g_PB[NNODE * CDIM];
__device__ __align__(16) float g_pd[EMAX * 4];        // pos_diff, padded float4
__device__ int   g_src[EMAX];
__device__ int   g_dst[EMAX];
__device__ int   g_deg[NNODE];
__device__ int   g_mode;                              // 1 = int64 indices, 0 = int32

__device__ __forceinline__ float elu_f(float v) {
    return v > 0.f ? v : expm1f(v);
}

// packed fp32x2 helpers (sm_100+)
__device__ __forceinline__ void ffma2(unsigned long long& d, unsigned long long a, unsigned long long b) {
    asm("fma.rn.f32x2 %0, %1, %2, %0;" : "+l"(d) : "l"(a), "l"(b));
}
__device__ __forceinline__ float usum(unsigned long long v) {
    float lo, hi;
    asm("mov.b64 {%0,%1}, %2;" : "=f"(lo), "=f"(hi) : "l"(v));
    return lo + hi;
}
// vector float2 reduction to global (sm_90+)
__device__ __forceinline__ void red_add_v2(float* addr, float x, float y) {
    asm volatile("red.global.add.v2.f32 [%0], {%1, %2};" :: "l"(addr), "f"(x), "f"(y) : "memory");
}

// ------------------------------------------------------------------ probe index dtype
__global__ void probe_kernel(const int* __restrict__ w) {
    if (threadIdx.x == 0 && blockIdx.x == 0) {
        bool all_odd_zero = true;
        for (int i = 1; i < 64; i += 2)
            if (w[i] != 0) { all_odd_zero = false; break; }
        g_mode = all_odd_zero ? 1 : 0;
    }
}

// ------------------------------------------------------------------ zero helpers
__global__ void zero_deg_kernel(int Nn) {
    for (int i = blockIdx.x * blockDim.x + threadIdx.x; i < Nn; i += gridDim.x * blockDim.x)
        g_deg[i] = 0;
}
__global__ void zero_agg_kernel(int n4) {
    float4* p = reinterpret_cast<float4*>(g_agg);
    for (int i = blockIdx.x * blockDim.x + threadIdx.x; i < n4; i += gridDim.x * blockDim.x)
        p[i] = make_float4(0.f, 0.f, 0.f, 0.f);
}

// ------------------------------------------------------------------ convert indices + pos_diff + degree
__global__ void convert_kernel(const int* __restrict__ w, const float* __restrict__ pos, int Ecnt) {
    int mode = g_mode;
    for (int e = blockIdx.x * blockDim.x + threadIdx.x; e < Ecnt; e += gridDim.x * blockDim.x) {
        int s, d;
        if (mode) { s = w[2 * e]; d = w[2 * (Ecnt + e)]; }
        else      { s = w[e];     d = w[Ecnt + e]; }
        s = min(max(s, 0), NNODE - 1);
        d = min(max(d, 0), NNODE - 1);
        g_src[e] = s;
        g_dst[e] = d;
        atomicAdd(&g_deg[d], 1);
        float4 pd;
        pd.x = pos[s * 3 + 0] - pos[d * 3 + 0];
        pd.y = pos[s * 3 + 1] - pos[d * 3 + 1];
        pd.z = pos[s * 3 + 2] - pos[d * 3 + 2];
        pd.w = 0.f;
        reinterpret_cast<float4*>(g_pd)[e] = pd;
    }
}

// ------------------------------------------------------------------ encoder
__global__ void encoder_kernel(const float* __restrict__ x,
                               const float* __restrict__ W0, const float* __restrict__ b0,
                               const float* __restrict__ W1, const float* __restrict__ b1,
                               int Nn) {
    __shared__ float sW1[4096];   // packed float2: (col j, col j+32)
    __shared__ float sW0[192];
    __shared__ float sb0[64];
    __shared__ float sb1[64];
    for (int t = threadIdx.x; t < 4096; t += blockDim.x) {
        int k = t >> 6, idx = t & 63, j = idx >> 1, half = idx & 1;
        sW1[t] = W1[k * 64 + j + (half << 5)];
    }
    for (int t = threadIdx.x; t < 192; t += blockDim.x) sW0[t] = W0[t];
    if (threadIdx.x < 64) { sb0[threadIdx.x] = b0[threadIdx.x]; sb1[threadIdx.x] = b1[threadIdx.x]; }
    __syncthreads();

    const float2* W1p = reinterpret_cast<const float2*>(sW1);
    int lane = threadIdx.x & 31;
    int wid  = threadIdx.x >> 5;
    int wg = blockIdx.x * (blockDim.x >> 5) + wid;
    int ws = gridDim.x * (blockDim.x >> 5);
    for (int n = wg; n < Nn; n += ws) {
        float x0 = x[n * 3 + 0], x1 = x[n * 3 + 1], x2 = x[n * 3 + 2];
        float hid0 = elu_f(x0 * sW0[lane]      + x1 * sW0[64 + lane]      + x2 * sW0[128 + lane]      + sb0[lane]);
        float hid1 = elu_f(x0 * sW0[lane + 32] + x1 * sW0[64 + lane + 32] + x2 * sW0[128 + lane + 32] + sb0[lane + 32]);
        float acc0 = sb1[lane], acc1 = sb1[lane + 32];
#pragma unroll
        for (int k = 0; k < 32; k++) {
            float v = __shfl_sync(0xffffffffu, hid0, k);
            float2 w = W1p[k * 32 + lane];
            acc0 += v * w.x; acc1 += v * w.y;
        }
#pragma unroll
        for (int k = 0; k < 32; k++) {
            float v = __shfl_sync(0xffffffffu, hid1, k);
            float2 w = W1p[(32 + k) * 32 + lane];
            acc0 += v * w.x; acc1 += v * w.y;
        }
        g_h[n * 64 + lane] = acc0;
        g_h[n * 64 + 32 + lane] = acc1;
    }
}

// ------------------------------------------------------------------ per-layer precompute:
// PA[n] = h[n]·(W0a+W0c),  PB[n] = h[n]·(W0b−W0c) + b0
// f32x2 K-packed; weights float4 = (w[k0][j], w[k1][j], w[k0][j+32], w[k1][j+32]).
__global__ void precompute_kernel(const float* __restrict__ E0, const float* __restrict__ eb0, int Nn) {
    extern __shared__ float sm[];
    float* sWA = sm;            // 4096
    float* sWB = sm + 4096;     // 4096
    float* sb0 = sm + 8192;     // 64
    float* stage = sm + 8256;   // 8 warps * 320 floats

    for (int t = threadIdx.x; t < 4096; t += blockDim.x) {
        int c = t & 3, lane_ = (t >> 2) & 31, kp = t >> 7;
        int k = 2 * kp + (c & 1);
        int col = lane_ + ((c & 2) ? 32 : 0);
        float wC = E0[(128 + k) * 64 + col];
        sWA[t] = E0[k * 64 + col] + wC;
        sWB[t] = E0[(64 + k) * 64 + col] - wC;
    }
    if (threadIdx.x < 64) sb0[threadIdx.x] = eb0[threadIdx.x];
    __syncthreads();

    int lane = threadIdx.x & 31;
    int wid  = threadIdx.x >> 5;
    float* wbase = stage + wid * 320;
    float2* nP = reinterpret_cast<float2*>(wbase);  // 32 kpairs * 5
    const ulonglong2* WAv = reinterpret_cast<const ulonglong2*>(sWA);
    const ulonglong2* WBv = reinterpret_cast<const ulonglong2*>(sWB);
    const unsigned long long* nU = reinterpret_cast<const unsigned long long*>(nP);

    int wg = blockIdx.x * (blockDim.x >> 5) + wid;
    int ws = gridDim.x * (blockDim.x >> 5);
    for (int base = wg * 4; base < Nn; base += ws * 4) {
#pragma unroll
        for (int i = 0; i < 4; i++) {
            int n = base + i;
            nP[lane * 5 + i] = (n < Nn) ? reinterpret_cast<const float2*>(g_h + n * 64)[lane]
                                        : make_float2(0.f, 0.f);
        }
        __syncwarp();

        unsigned long long aA0[4] = {0,0,0,0}, aA1[4] = {0,0,0,0};
        unsigned long long aB0[4] = {0,0,0,0}, aB1[4] = {0,0,0,0};
#pragma unroll 4
        for (int kp = 0; kp < 32; kp++) {
            ulonglong2 wa = WAv[kp * 32 + lane];
            ulonglong2 wb = WBv[kp * 32 + lane];
#pragma unroll
            for (int i = 0; i < 4; i++) {
                unsigned long long v = nU[kp * 5 + i];
                ffma2(aA0[i], v, wa.x); ffma2(aA1[i], v, wa.y);
                ffma2(aB0[i], v, wb.x); ffma2(aB1[i], v, wb.y);
            }
        }
        float b0a = sb0[lane], b0b = sb0[lane + 32];
#pragma unroll
        for (int i = 0; i < 4; i++) {
            int n = base + i;
            if (n < Nn) {
                g_PA[n * 64 + lane]      = usum(aA0[i]);
                g_PA[n * 64 + 32 + lane] = usum(aA1[i]);
                g_PB[n * 64 + lane]      = usum(aB0[i]) + b0a;
                g_PB[n * 64 + 32 + lane] = usum(aB1[i]) + b0b;
            }
        }
        __syncwarp();
    }
}

// ------------------------------------------------------------------ edge scatter (no SMEM!)
// hidden = elu(PA[src] + PB[dst] + pos_diff·Wp)  → red.v2 into g_agg[dst]
// lane l handles channels (2l, 2l+1).
__global__ void edge_scatter_kernel(const float* __restrict__ Wp, int Ecnt) {
    int lane = threadIdx.x & 31;
    int wid  = threadIdx.x >> 5;
    float2 wp0 = reinterpret_cast<const float2*>(Wp)[lane];
    float2 wp1 = reinterpret_cast<const float2*>(Wp + 64)[lane];
    float2 wp2 = reinterpret_cast<const float2*>(Wp + 128)[lane];

    int wg = blockIdx.x * (blockDim.x >> 5) + wid;
    int ws = gridDim.x * (blockDim.x >> 5);
    for (int base = wg * 4; base < Ecnt; base += ws * 4) {
        float2 pa[4], pb[4];
        float4 pd[4];
        int ds[4];
#pragma unroll
        for (int i = 0; i < 4; i++) {
            int e = base + i;
            if (e < Ecnt) {
                int s = __ldg(&g_src[e]);
                int d = __ldg(&g_dst[e]);
                ds[i] = d;
                pa[i] = reinterpret_cast<const float2*>(g_PA + s * 64)[lane];
                pb[i] = reinterpret_cast<const float2*>(g_PB + d * 64)[lane];
                pd[i] = reinterpret_cast<const float4*>(g_pd)[e];
            } else {
                ds[i] = -1;
                pa[i] = make_float2(0.f, 0.f); pb[i] = make_float2(0.f, 0.f);
                pd[i] = make_float4(0.f, 0.f, 0.f, 0.f);
            }
        }
#pragma unroll
        for (int i = 0; i < 4; i++) {
            if (ds[i] >= 0) {
                float hx = pa[i].x + pb[i].x + pd[i].x * wp0.x + pd[i].y * wp1.x + pd[i].z * wp2.x;
                float hy = pa[i].y + pb[i].y + pd[i].x * wp0.y + pd[i].y * wp1.y + pd[i].z * wp2.y;
                hx = elu_f(hx); hy = elu_f(hy);
                red_add_v2(&g_agg[ds[i] * 64 + 2 * lane], hx, hy);
            }
        }
    }
}

// ------------------------------------------------------------------ fused node update:
// agg = Hsum[n]·eW1 + deg[n]·eb1
// u   = elu([h, agg]·nW0 + nb0)·nW1 + nb1 ;  h += u
__global__ void node_fused_kernel(const float* __restrict__ E1, const float* __restrict__ eb1,
                                  const float* __restrict__ W0, const float* __restrict__ b0,
                                  const float* __restrict__ W1, const float* __restrict__ b1,
                                  int Nn) {
    extern __shared__ float sm[];
    float* sE1 = sm;                 // 4096
    float* sW0 = sm + 4096;          // 8192
    float* sW1 = sm + 12288;         // 4096
    float* seb1 = sm + 16384;        // 64
    float* snb0 = sm + 16448;        // 64
    float* snb1 = sm + 16512;        // 64
    float* stage = sm + 16576;       // 8 warps * 640

    for (int t = threadIdx.x; t < 4096; t += blockDim.x) {
        int c = t & 3, lane_ = (t >> 2) & 31, kp = t >> 7;
        int k = 2 * kp + (c & 1);
        int col = lane_ + ((c & 2) ? 32 : 0);
        sE1[t] = E1[k * 64 + col];
        sW1[t] = W1[k * 64 + col];
    }
    for (int t = threadIdx.x; t < 8192; t += blockDim.x) {
        int c = t & 3, lane_ = (t >> 2) & 31, kp = t >> 7;
        int k = 2 * kp + (c & 1);
        int col = lane_ + ((c & 2) ? 32 : 0);
        sW0[t] = W0[k * 64 + col];
    }
    if (threadIdx.x < 64) {
        seb1[threadIdx.x] = eb1[threadIdx.x];
        snb0[threadIdx.x] = b0[threadIdx.x];
        snb1[threadIdx.x] = b1[threadIdx.x];
    }
    __syncthreads();

    int lane = threadIdx.x & 31;
    int wid  = threadIdx.x >> 5;
    float* wbase = stage + wid * 640;
    float2* nP = reinterpret_cast<float2*>(wbase);  // kpairs 0..31 = h, 32..63 = Hsum→agg
    const ulonglong2* E1v = reinterpret_cast<const ulonglong2*>(sE1);
    const ulonglong2* W0v = reinterpret_cast<const ulonglong2*>(sW0);
    const ulonglong2* W1v = reinterpret_cast<const ulonglong2*>(sW1);
    const unsigned long long* nU = reinterpret_cast<const unsigned long long*>(nP);
    float* hF = wbase;

    int wg = blockIdx.x * (blockDim.x >> 5) + wid;
    int ws = gridDim.x * (blockDim.x >> 5);
    for (int base = wg * 4; base < Nn; base += ws * 4) {
        float degf[4];
#pragma unroll
        for (int i = 0; i < 4; i++) {
            int n = base + i;
            if (n < Nn) {
                nP[lane * 5 + i]        = reinterpret_cast<const float2*>(g_h + n * 64)[lane];
                nP[(32 + lane) * 5 + i] = reinterpret_cast<const float2*>(g_agg + n * 64)[lane];
                degf[i] = (float)__ldg(&g_deg[n]);
            } else {
                nP[lane * 5 + i]        = make_float2(0.f, 0.f);
                nP[(32 + lane) * 5 + i] = make_float2(0.f, 0.f);
                degf[i] = 0.f;
            }
        }
        __syncwarp();

        // ---- GEMM1: agg = Hsum·E1 + deg·eb1
        unsigned long long a0[4] = {0,0,0,0}, a1[4] = {0,0,0,0};
#pragma unroll 4
        for (int kp = 0; kp < 32; kp++) {
            ulonglong2 w = E1v[kp * 32 + lane];
#pragma unroll
            for (int i = 0; i < 4; i++) {
                unsigned long long v = nU[(32 + kp) * 5 + i];
                ffma2(a0[i], v, w.x); ffma2(a1[i], v, w.y);
            }
        }
        float e1a = seb1[lane], e1b = seb1[lane + 32];
        float aggL[4], aggH[4];
#pragma unroll
        for (int i = 0; i < 4; i++) {
            aggL[i] = usum(a0[i]) + degf[i] * e1a;   // channel lane
            aggH[i] = usum(a1[i]) + degf[i] * e1b;   // channel lane+32
        }
        __syncwarp();
        {
            // restage agg into kpairs 32..63: combined k = 64 + k_agg
            int rL = ((32 + (lane >> 1)) * 5) * 2 + (lane & 1);   // k_agg = lane
            int rH = ((48 + (lane >> 1)) * 5) * 2 + (lane & 1);   // k_agg = lane+32
#pragma unroll
            for (int i = 0; i < 4; i++) {
                hF[rL + 2 * i] = aggL[i];
                hF[rH + 2 * i] = aggH[i];
            }
        }
        __syncwarp();

        // ---- GEMM2: hidden = elu([h, agg]·W0 + b0)
        unsigned long long c0[4] = {0,0,0,0}, c1[4] = {0,0,0,0};
#pragma unroll 4
        for (int kp = 0; kp < 64; kp++) {
            ulonglong2 w = W0v[kp * 32 + lane];
#pragma unroll
            for (int i = 0; i < 4; i++) {
                unsigned long long v = nU[kp * 5 + i];
                ffma2(c0[i], v, w.x); ffma2(c1[i], v, w.y);
            }
        }
        float b0a = snb0[lane], b0b = snb0[lane + 32];
        float hL[4], hH[4];
#pragma unroll
        for (int i = 0; i < 4; i++) {
            hL[i] = elu_f(usum(c0[i]) + b0a);
            hH[i] = elu_f(usum(c1[i]) + b0b);
        }
        __syncwarp();
        {
            // restage hidden into kpairs 0..31 (overwrites h staging; g_h re-read later)
            int rL = ((lane >> 1) * 5) * 2 + (lane & 1);
            int rH = ((16 + (lane >> 1)) * 5) * 2 + (lane & 1);
#pragma unroll
            for (int i = 0; i < 4; i++) {
                hF[rL + 2 * i] = hL[i];
                hF[rH + 2 * i] = hH[i];
            }
        }
        __syncwarp();

        // ---- GEMM3: u = hidden·W1 + b1 ; h += u
        unsigned long long d0[4] = {0,0,0,0}, d1[4] = {0,0,0,0};
#pragma unroll 4
        for (int kp = 0; kp < 32; kp++) {
            ulonglong2 w = W1v[kp * 32 + lane];
#pragma unroll
            for (int i = 0; i < 4; i++) {
                unsigned long long v = nU[kp * 5 + i];
                ffma2(d0[i], v, w.x); ffma2(d1[i], v, w.y);
            }
        }
        float b1a = snb1[lane], b1b = snb1[lane + 32];
#pragma unroll
        for (int i = 0; i < 4; i++) {
            int n = base + i;
            if (n < Nn) {
                float old0 = g_h[n * 64 + lane];
                float old1 = g_h[n * 64 + 32 + lane];
                g_h[n * 64 + lane]      = old0 + usum(d0[i]) + b1a;
                g_h[n * 64 + 32 + lane] = old1 + usum(d1[i]) + b1b;
            }
        }
        __syncwarp();
    }
}

// ------------------------------------------------------------------ decoder
__global__ void decoder_kernel(const float* __restrict__ W0, const float* __restrict__ b0,
                               const float* __restrict__ W1, const float* __restrict__ b1,
                               float* __restrict__ out, int Nn) {
    __shared__ float sW0[4096];
    __shared__ float sW1[192];
    __shared__ float sb0[64];
    __shared__ float sb1v[3];
    for (int t = threadIdx.x; t < 4096; t += blockDim.x) {
        int k = t >> 6, idx = t & 63, j = idx >> 1, half = idx & 1;
        sW0[t] = W0[k * 64 + j + (half << 5)];
    }
    for (int t = threadIdx.x; t < 192; t += blockDim.x) sW1[t] = W1[t];
    if (threadIdx.x < 64) sb0[threadIdx.x] = b0[threadIdx.x];
    if (threadIdx.x < 3)  sb1v[threadIdx.x] = b1[threadIdx.x];
    __syncthreads();

    const float2* W0p = reinterpret_cast<const float2*>(sW0);
    int lane = threadIdx.x & 31, wid = threadIdx.x >> 5;
    int wg = blockIdx.x * (blockDim.x >> 5) + wid;
    int ws = gridDim.x * (blockDim.x >> 5);
    for (int n = wg; n < Nn; n += ws) {
        float h0 = g_h[n * 64 + lane], h1 = g_h[n * 64 + 32 + lane];
        float acc0 = sb0[lane], acc1 = sb0[lane + 32];
#pragma unroll
        for (int k = 0; k < 32; k++) { float v = __shfl_sync(~0u, h0, k); float2 w = W0p[k * 32 + lane];        acc0 += v * w.x; acc1 += v * w.y; }
#pragma unroll
        for (int k = 0; k < 32; k++) { float v = __shfl_sync(~0u, h1, k); float2 w = W0p[(32 + k) * 32 + lane]; acc0 += v * w.x; acc1 += v * w.y; }
        float hid0 = elu_f(acc0), hid1 = elu_f(acc1);
        float p0 = hid0 * sW1[lane * 3 + 0] + hid1 * sW1[(lane + 32) * 3 + 0];
        float p1 = hid0 * sW1[lane * 3 + 1] + hid1 * sW1[(lane + 32) * 3 + 1];
        float p2 = hid0 * sW1[lane * 3 + 2] + hid1 * sW1[(lane + 32) * 3 + 2];
#pragma unroll
        for (int off = 16; off; off >>= 1) {
            p0 += __shfl_xor_sync(~0u, p0, off);
            p1 += __shfl_xor_sync(~0u, p1, off);
            p2 += __shfl_xor_sync(~0u, p2, off);
        }
        if (lane == 0) {
            out[n * 3 + 0] = p0 + sb1v[0];
            out[n * 3 + 1] = p1 + sb1v[1];
            out[n * 3 + 2] = p2 + sb1v[2];
        }
    }
}

// ------------------------------------------------------------------ launch
extern "C" void kernel_launch(void* const* d_in, const int* in_sizes, int n_in,
                              void* d_out, int out_size) {
    const float* x      = (const float*)d_in[0];
    const float* pos    = (const float*)d_in[1];
    const int*   ei     = (const int*)d_in[2];   // dtype auto-detected on device
    const float* enc_W0 = (const float*)d_in[3];
    const float* enc_b0 = (const float*)d_in[4];
    const float* enc_W1 = (const float*)d_in[5];
    const float* enc_b1 = (const float*)d_in[6];
    const float* dec_W0 = (const float*)d_in[7];
    const float* dec_b0 = (const float*)d_in[8];
    const float* dec_W1 = (const float*)d_in[9];
    const float* dec_b1 = (const float*)d_in[10];
    const float* eW0    = (const float*)d_in[11];
    const float* eb0    = (const float*)d_in[12];
    const float* eW1    = (const float*)d_in[13];
    const float* eb1    = (const float*)d_in[14];
    const float* nW0    = (const float*)d_in[15];
    const float* nb0    = (const float*)d_in[16];
    const float* nW1    = (const float*)d_in[17];
    const float* nb1    = (const float*)d_in[18];

    int Nn   = in_sizes[0] / 3;
    int Ecnt = in_sizes[2] / 2;
    if (Ecnt > EMAX) Ecnt = EMAX;
    float* out = (float*)d_out;

    const int PRE_SMEM  = (8256 + 8 * 320) * 4;    // 43,264 B
    const int NODE_SMEM = (16576 + 8 * 640) * 4;   // 86,784 B
    cudaFuncSetAttribute(precompute_kernel, cudaFuncAttributeMaxDynamicSharedMemorySize, PRE_SMEM);
    cudaFuncSetAttribute(node_fused_kernel, cudaFuncAttributeMaxDynamicSharedMemorySize, NODE_SMEM);

    const int TPB = 256;

    probe_kernel<<<1, 32>>>(ei);
    zero_deg_kernel<<<148, TPB>>>(Nn);
    convert_kernel<<<444, TPB>>>(ei, pos, Ecnt);
    encoder_kernel<<<444, TPB>>>(x, enc_W0, enc_b0, enc_W1, enc_b1, Nn);
    for (int l = 0; l < 2; l++) {
        const float* E0l = eW0 + (size_t)l * 195 * 64;
        precompute_kernel<<<296, TPB, PRE_SMEM>>>(E0l, eb0 + l * 64, Nn);
        zero_agg_kernel<<<444, TPB>>>(Nn * 64 / 4);
        edge_scatter_kernel<<<592, TPB>>>(E0l + 192 * 64, Ecnt);
        node_fused_kernel<<<296, TPB, NODE_SMEM>>>(eW1 + (size_t)l * 64 * 64, eb1 + l * 64,
                                                   nW0 + (size_t)l * 128 * 64, nb0 + l * 64,
                                                   nW1 + (size_t)l * 64 * 64,  nb1 + l * 64,
                                                   Nn);
    }
    decoder_kernel<<<444, TPB>>>(dec_W0, dec_b0, dec_W1, dec_b1, out, Nn);
}